// round 16
// baseline (speedup 1.0000x reference)
#include <cuda_runtime.h>
#include <cuda_fp16.h>
#include <cstdint>
#include <math.h>

#define BATCH 32
#define C 512
#define L 4096
#define GROUPS 32
#define CPG 16
#define EPS 1e-5f

// ---------------- scratch (device globals; allocation-free rule) -----------
__device__ __align__(256) __half g_xnh   [(size_t)BATCH * C * L];   // [C,L] normed
__device__ __align__(256) __half g_gram  [(size_t)BATCH * C * C];   // G = xn·xn^T
__device__ __align__(256) __half g_t1    [(size_t)BATCH * C * C];   // Wq·G
__device__ __align__(256) __half g_logits[(size_t)BATCH * C * C];
__device__ __align__(256) __half g_attn  [(size_t)BATCH * C * C];
__device__ __align__(256) __half g_pm    [(size_t)BATCH * C * C];   // M = P·attn
__device__ __align__(256) __half g_mwv   [(size_t)BATCH * C * C];   // M·Wv + I
__device__ __align__(256) __half g_wh    [(size_t)4 * C * C];       // qkv_w + proj_w (fp16)
__device__ __align__(256) float  g_s     [(size_t)BATCH * C];       // row sums of xn
__device__ __align__(256) float  g_uv    [(size_t)BATCH * 1024];    // [v=Wq·s | u=Wk·s+L·bk]
__device__ __align__(256) float  g_e     [(size_t)BATCH * C];       // e = M·bv + proj_b

// ---------------- PTX helpers ----------------------------------------------
__device__ __forceinline__ uint32_t smem_u32(const void* p) {
    uint32_t a;
    asm("{ .reg .u64 t; cvta.to.shared.u64 t, %1; cvt.u32.u64 %0, t; }" : "=r"(a) : "l"(p));
    return a;
}
#define CP_ASYNC16(dst, src) \
    asm volatile("cp.async.cg.shared.global [%0], [%1], 16;" :: "r"(dst), "l"(src) : "memory")
#define CP_COMMIT() asm volatile("cp.async.commit_group;" ::: "memory")
#define CP_WAIT1()  asm volatile("cp.async.wait_group 1;" ::: "memory")
#define CP_WAIT0()  asm volatile("cp.async.wait_group 0;" ::: "memory")

__device__ __forceinline__ void ldsm_x4(uint32_t (&r)[4], uint32_t addr) {
    asm volatile("ldmatrix.sync.aligned.m8n8.x4.shared.b16 {%0,%1,%2,%3}, [%4];"
        : "=r"(r[0]), "=r"(r[1]), "=r"(r[2]), "=r"(r[3]) : "r"(addr));
}
__device__ __forceinline__ void ldsm_x4_t(uint32_t (&r)[4], uint32_t addr) {
    asm volatile("ldmatrix.sync.aligned.m8n8.x4.trans.shared.b16 {%0,%1,%2,%3}, [%4];"
        : "=r"(r[0]), "=r"(r[1]), "=r"(r[2]), "=r"(r[3]) : "r"(addr));
}
__device__ __forceinline__ void mma16816(float (&d)[4], const uint32_t (&a)[4],
                                         uint32_t b0, uint32_t b1) {
    asm volatile(
        "mma.sync.aligned.m16n8k16.row.col.f32.f16.f16.f32 "
        "{%0,%1,%2,%3}, {%4,%5,%6,%7}, {%8,%9}, {%0,%1,%2,%3};"
        : "+f"(d[0]), "+f"(d[1]), "+f"(d[2]), "+f"(d[3])
        : "r"(a[0]), "r"(a[1]), "r"(a[2]), "r"(a[3]), "r"(b0), "r"(b1));
}

// ---------------- GroupNorm (+weight convert, +row sums) fused launch -------
__global__ __launch_bounds__(256) void gn_cvt_kernel(
    const float* __restrict__ x, const float* __restrict__ gw,
    const float* __restrict__ gb, __half* __restrict__ xnh,
    const float* __restrict__ qkvw, const float* __restrict__ projw,
    __half* __restrict__ wh, float* __restrict__ srow)
{
    const int bid = blockIdx.x;
    const int tid = threadIdx.x;

    if (bid >= BATCH * GROUPS) {
        const int i4 = (bid - BATCH * GROUPS) * 256 + tid;
        const int n_qkv4 = 3 * C * C / 4;
        float4 v;
        if (i4 < n_qkv4) v = ((const float4*)qkvw)[i4];
        else             v = ((const float4*)projw)[i4 - n_qkv4];
        __half2* o = (__half2*)(wh + (size_t)i4 * 4);
        o[0] = __floats2half2_rn(v.x, v.y);
        o[1] = __floats2half2_rn(v.z, v.w);
        return;
    }

    const int b = bid / GROUPS;
    const int g = bid % GROUPS;
    const size_t base = ((size_t)b * C + (size_t)g * CPG) * L;
    const float4* px4 = (const float4*)(x + base);
    __half2* outh = (__half2*)(xnh + base);
    const int n4 = CPG * L / 4;

    float s = 0.f, ss = 0.f;
    for (int i = tid; i < n4; i += 256) {
        float4 v = px4[i];
        s  += v.x + v.y + v.z + v.w;
        ss += v.x*v.x + v.y*v.y + v.z*v.z + v.w*v.w;
    }
    __shared__ float sh_s[32], sh_ss[32];
    for (int o = 16; o > 0; o >>= 1) {
        s  += __shfl_down_sync(0xffffffff, s, o);
        ss += __shfl_down_sync(0xffffffff, ss, o);
    }
    if ((tid & 31) == 0) { sh_s[tid >> 5] = s; sh_ss[tid >> 5] = ss; }
    __syncthreads();
    if (tid < 32) {
        s  = (tid < 8) ? sh_s[tid]  : 0.f;
        ss = (tid < 8) ? sh_ss[tid] : 0.f;
        for (int o = 4; o > 0; o >>= 1) {
            s  += __shfl_down_sync(0xffffffff, s, o);
            ss += __shfl_down_sync(0xffffffff, ss, o);
        }
        if (tid == 0) { sh_s[0] = s; sh_ss[0] = ss; }
    }
    __syncthreads();
    const float inv_n = 1.f / (float)(CPG * L);
    const float mean  = sh_s[0] * inv_n;
    const float var   = sh_ss[0] * inv_n - mean * mean;
    const float rstd  = rsqrtf(var + EPS);

    float csum[16];
    #pragma unroll
    for (int c = 0; c < 16; c++) csum[c] = 0.f;

    for (int j = 0; j < 64; j++) {
        const int i = tid + 256 * j;
        const int ch = j >> 2;
        const float w = gw[g * CPG + ch] * rstd;
        const float bb = gb[g * CPG + ch] - mean * w;
        float4 v = px4[i];
        const float e0 = fmaf(v.x, w, bb), e1 = fmaf(v.y, w, bb);
        const float e2 = fmaf(v.z, w, bb), e3 = fmaf(v.w, w, bb);
        outh[i * 2 + 0] = __floats2half2_rn(e0, e1);
        outh[i * 2 + 1] = __floats2half2_rn(e2, e3);
        csum[ch] += (e0 + e1) + (e2 + e3);
    }
    __shared__ float s_part[16][8];
    #pragma unroll
    for (int c = 0; c < 16; c++) {
        float t = csum[c];
        for (int o = 16; o > 0; o >>= 1) t += __shfl_down_sync(0xffffffff, t, o);
        if ((tid & 31) == 0) s_part[c][tid >> 5] = t;
    }
    __syncthreads();
    if (tid < 16) {
        float t = 0.f;
        #pragma unroll
        for (int w8 = 0; w8 < 8; w8++) t += s_part[tid][w8];
        srow[b * C + g * CPG + tid] = t;
    }
}

// ---------------- Row softmax (fp16 in, fp16 out) ---------------------------
__global__ __launch_bounds__(128) void softmax512_kernel(
    const __half* __restrict__ logits, __half* __restrict__ attn)
{
    const size_t row = blockIdx.x;
    const __half2* p = (const __half2*)(logits + row * C);
    const int tid = threadIdx.x;

    float2 a = __half22float2(p[tid * 2 + 0]);
    float2 b = __half22float2(p[tid * 2 + 1]);
    float m = fmaxf(fmaxf(a.x, a.y), fmaxf(b.x, b.y));
    __shared__ float sh[4];
    for (int o = 16; o > 0; o >>= 1) m = fmaxf(m, __shfl_xor_sync(0xffffffff, m, o));
    if ((tid & 31) == 0) sh[tid >> 5] = m;
    __syncthreads();
    m = fmaxf(fmaxf(sh[0], sh[1]), fmaxf(sh[2], sh[3]));

    a.x = expf(a.x - m); a.y = expf(a.y - m);
    b.x = expf(b.x - m); b.y = expf(b.y - m);
    float s = a.x + a.y + b.x + b.y;
    for (int o = 16; o > 0; o >>= 1) s += __shfl_xor_sync(0xffffffff, s, o);
    __shared__ float shs[4];
    if ((tid & 31) == 0) shs[tid >> 5] = s;
    __syncthreads();
    s = shs[0] + shs[1] + shs[2] + shs[3];
    const float inv = 1.f / s;

    __half2* o2 = (__half2*)(attn + row * C);
    o2[tid * 2 + 0] = __floats2half2_rn(a.x * inv, a.y * inv);
    o2[tid * 2 + 1] = __floats2half2_rn(b.x * inv, b.y * inv);
}

// ---------------- fp16 tensor-core GEMM core (128x128 tile) -----------------
#define STAGE_BYTES 32768          // A 16KB + B 16KB
#define GEMM_SMEM  (3 * STAGE_BYTES)

__device__ __forceinline__ void load_A(const __half* __restrict__ gA, int lda,
                                       uint32_t st, int tid)
{
    #pragma unroll
    for (int j = 0; j < 8; j++) {
        const int slot = tid + 128 * j;
        const int row  = slot >> 3;
        const int c    = slot & 7;
        const uint32_t off = (uint32_t)row * 128u + (uint32_t)((c ^ (row & 7)) << 4);
        CP_ASYNC16(st + off, gA + (size_t)row * lda + c * 8);
    }
}
__device__ __forceinline__ void load_B_t(const __half* __restrict__ gB, int ldb,
                                         uint32_t st, int tid)
{
    #pragma unroll
    for (int j = 0; j < 8; j++) {
        const int slot = tid + 128 * j;
        const int row  = slot >> 4;           // 0..63 (k)
        const int c    = slot & 15;           // 16B chunk (n/8)
        const uint32_t off = (uint32_t)((row * 2 + (c >> 3)) * 128)
                           + (uint32_t)(((c & 7) ^ (row & 7)) << 4);
        CP_ASYNC16(st + off, gB + (size_t)row * ldb + c * 8);
    }
}

// 128x128 trans-B GEMM with per-batch row bias (used only for the final out)
template<typename OutT>
__global__ __launch_bounds__(128, 2) void hgemm_out_kernel(
    const __half* __restrict__ A, long long sA, int lda,
    const __half* __restrict__ B, long long sB, int ldb,
    OutT* __restrict__ D, long long sD, int ldd,
    int K,
    const float* __restrict__ bias, long long sBias)
{
    extern __shared__ __align__(128) char smem[];
    const uint32_t sbase = smem_u32(smem);
    const int bz = blockIdx.z;
    A += (size_t)bz * sA;
    B += (size_t)bz * sB;
    D += (size_t)bz * sD;
    bias += (size_t)bz * sBias;

    const int bm = blockIdx.y * 128;
    const int bn = blockIdx.x * 128;
    const int tid = threadIdx.x;
    const int lane = tid & 31;
    const int wid = tid >> 5;
    const int wm = wid & 1;
    const int wn = wid >> 1;

    const __half* gA = A + (size_t)bm * lda;
    const __half* gB = B + bn;
    const int T = K >> 6;

    const int a_row_lo = lane & 15;
    const int a_sel    = lane >> 4;
    const int bt_k_lo  = lane & 15;
    const int bt_n8    = (lane >> 4) << 3;

    float acc[4][8][4];
    #pragma unroll
    for (int i = 0; i < 4; i++)
        #pragma unroll
        for (int j = 0; j < 8; j++)
            #pragma unroll
            for (int q = 0; q < 4; q++) acc[i][j][q] = 0.f;

    #pragma unroll
    for (int s = 0; s < 2; s++) {
        const uint32_t st = sbase + s * STAGE_BYTES;
        load_A(gA + s * 64, lda, st, tid);
        load_B_t(gB + (size_t)(s * 64) * ldb, ldb, st + 16384, tid);
        CP_COMMIT();
    }

    for (int t = 0; t < T; t++) {
        if (t < T - 1) CP_WAIT1(); else CP_WAIT0();
        __syncthreads();

        if (t + 2 < T) {
            const int s = t + 2;
            const uint32_t st = sbase + (s % 3) * STAGE_BYTES;
            load_A(gA + s * 64, lda, st, tid);
            load_B_t(gB + (size_t)(s * 64) * ldb, ldb, st + 16384, tid);
            CP_COMMIT();
        }

        const uint32_t stA = sbase + (t % 3) * STAGE_BYTES;
        const uint32_t stB = stA + 16384;

        #pragma unroll
        for (int ks = 0; ks < 4; ks++) {
            uint32_t aF[4][4];
            uint32_t bF[4][4];
            #pragma unroll
            for (int mi = 0; mi < 4; mi++) {
                const int row = wm * 64 + mi * 16 + a_row_lo;
                const int ch  = ks * 2 + a_sel;
                ldsm_x4(aF[mi], stA + (uint32_t)row * 128u + (uint32_t)((ch ^ (row & 7)) << 4));
            }
            const int krow = ks * 16 + bt_k_lo;
            #pragma unroll
            for (int nb = 0; nb < 4; nb++) {
                const int n = wn * 64 + nb * 16 + bt_n8;
                const uint32_t addr = stB
                    + (uint32_t)((krow * 2 + (n >> 6)) * 128)
                    + (uint32_t)((((n >> 3) & 7) ^ (krow & 7)) << 4);
                ldsm_x4_t(bF[nb], addr);
            }
            #pragma unroll
            for (int mi = 0; mi < 4; mi++)
                #pragma unroll
                for (int nj = 0; nj < 8; nj++)
                    mma16816(acc[mi][nj], aF[mi],
                             bF[nj >> 1][(nj & 1) * 2], bF[nj >> 1][(nj & 1) * 2 + 1]);
        }
    }

    const int m0 = bm + wm * 64;
    const int n0 = bn + wn * 64;
    #pragma unroll
    for (int mi = 0; mi < 4; mi++) {
        const int r0 = m0 + mi * 16 + (lane >> 2);
        const int r1 = r0 + 8;
        const float br0 = bias[r0], br1 = bias[r1];
        #pragma unroll
        for (int nj = 0; nj < 8; nj++) {
            const int c0 = n0 + nj * 8 + (lane & 3) * 2;
            *reinterpret_cast<float2*>(&D[(size_t)r0 * ldd + c0]) =
                make_float2(acc[mi][nj][0] + br0, acc[mi][nj][1] + br0);
            *reinterpret_cast<float2*>(&D[(size_t)r1 * ldd + c0]) =
                make_float2(acc[mi][nj][2] + br1, acc[mi][nj][3] + br1);
        }
    }
}

// ---------------- 64x64 GEMM core ------------------------------------------
// 128 thr = 4 warps (2m x 2n), warp tile 32x32. 3-stage, stage = 16KB.
// BIAS_MODE: 0 none, 3 rank-1 logits epilogue. B_TRANS, ADD_IDENT as before.
#define G64_STAGE 16384
#define G64_SMEM  (3 * G64_STAGE)

__device__ __forceinline__ void load_64(const __half* __restrict__ g, int ld,
                                        uint32_t st, int tid)
{
    #pragma unroll
    for (int j = 0; j < 4; j++) {
        const int slot = tid + 128 * j;       // 0..511
        const int row  = slot >> 3;           // 0..63
        const int c    = slot & 7;
        const uint32_t off = (uint32_t)row * 128u + (uint32_t)((c ^ (row & 7)) << 4);
        CP_ASYNC16(st + off, g + (size_t)row * ld + c * 8);
    }
}

template<int BIAS_MODE, bool B_TRANS, bool ADD_IDENT>
__device__ __forceinline__ void gemm64_core(
    int ix, int iy, int bz, uint32_t sbase,
    const __half* __restrict__ A, long long sA, int lda,
    const __half* __restrict__ B, long long sB, int ldb,
    __half* __restrict__ D, long long sD, int ldd,
    int K,
    const float* __restrict__ bias, const float* __restrict__ uv,
    float alpha)
{
    A += (size_t)bz * sA;
    B += (size_t)bz * sB;
    D += (size_t)bz * sD;
    if (BIAS_MODE == 3) uv += (size_t)bz * 1024;

    const int bm = iy * 64;
    const int bn = ix * 64;
    const int tid = threadIdx.x;
    const int lane = tid & 31;
    const int wid = tid >> 5;
    const int wm = wid & 1;
    const int wn = wid >> 1;

    const __half* gA = A + (size_t)bm * lda;
    const __half* gB = B_TRANS ? (B + bn) : (B + (size_t)bn * ldb);
    const int T = K >> 6;

    const int a_row_lo = lane & 15;
    const int a_sel    = lane >> 4;
    const int b_row_lo = (lane & 7) + ((lane >> 4) << 3);
    const int b_sel    = (lane >> 3) & 1;
    const int bt_k_lo  = lane & 15;
    const int bt_n8    = (lane >> 4) << 3;

    float acc[2][4][4];
    #pragma unroll
    for (int i = 0; i < 2; i++)
        #pragma unroll
        for (int j = 0; j < 4; j++)
            #pragma unroll
            for (int q = 0; q < 4; q++) acc[i][j][q] = 0.f;

    #pragma unroll
    for (int s = 0; s < 2; s++) {
        const uint32_t st = sbase + s * G64_STAGE;
        load_64(gA + s * 64, lda, st, tid);
        if (B_TRANS) load_64(gB + (size_t)(s * 64) * ldb, ldb, st + 8192, tid);
        else         load_64(gB + s * 64, ldb, st + 8192, tid);
        CP_COMMIT();
    }

    for (int t = 0; t < T; t++) {
        if (t < T - 1) CP_WAIT1(); else CP_WAIT0();
        __syncthreads();

        if (t + 2 < T) {
            const int s = t + 2;
            const uint32_t st = sbase + (s % 3) * G64_STAGE;
            load_64(gA + s * 64, lda, st, tid);
            if (B_TRANS) load_64(gB + (size_t)(s * 64) * ldb, ldb, st + 8192, tid);
            else         load_64(gB + s * 64, ldb, st + 8192, tid);
            CP_COMMIT();
        }

        const uint32_t stA = sbase + (t % 3) * G64_STAGE;
        const uint32_t stB = stA + 8192;

        #pragma unroll
        for (int ks = 0; ks < 4; ks++) {
            uint32_t aF[2][4];
            uint32_t bF[2][4];
            #pragma unroll
            for (int mi = 0; mi < 2; mi++) {
                const int row = wm * 32 + mi * 16 + a_row_lo;
                const int ch  = ks * 2 + a_sel;
                ldsm_x4(aF[mi], stA + (uint32_t)row * 128u + (uint32_t)((ch ^ (row & 7)) << 4));
            }
            if (B_TRANS) {
                const int krow = ks * 16 + bt_k_lo;
                #pragma unroll
                for (int nb = 0; nb < 2; nb++) {
                    const int n = wn * 32 + nb * 16 + bt_n8;   // 0..63
                    const uint32_t addr = stB + (uint32_t)krow * 128u
                        + (uint32_t)((((n >> 3) & 7) ^ (krow & 7)) << 4);
                    ldsm_x4_t(bF[nb], addr);
                }
            } else {
                #pragma unroll
                for (int nb = 0; nb < 2; nb++) {
                    const int row = wn * 32 + nb * 16 + b_row_lo;
                    const int ch  = ks * 2 + b_sel;
                    ldsm_x4(bF[nb], stB + (uint32_t)row * 128u + (uint32_t)((ch ^ (row & 7)) << 4));
                }
            }
            #pragma unroll
            for (int mi = 0; mi < 2; mi++)
                #pragma unroll
                for (int nj = 0; nj < 4; nj++)
                    mma16816(acc[mi][nj], aF[mi],
                             bF[nj >> 1][(nj & 1) * 2], bF[nj >> 1][(nj & 1) * 2 + 1]);
        }
    }

    const int m0 = bm + wm * 32;
    const int n0 = bn + wn * 32;
    #pragma unroll
    for (int mi = 0; mi < 2; mi++) {
        const int r0 = m0 + mi * 16 + (lane >> 2);
        const int r1 = r0 + 8;
        float bq0 = 0.f, bq1 = 0.f, vv0 = 0.f, vv1 = 0.f;
        if (BIAS_MODE == 3) {
            bq0 = bias[r0]; bq1 = bias[r1];
            vv0 = uv[r0];   vv1 = uv[r1];
        }
        #pragma unroll
        for (int nj = 0; nj < 4; nj++) {
            const int c0 = n0 + nj * 8 + (lane & 3) * 2;
            float v0 = acc[mi][nj][0];
            float v1 = acc[mi][nj][1];
            float v2 = acc[mi][nj][2];
            float v3 = acc[mi][nj][3];
            if (BIAS_MODE == 3) {
                const float bkc0 = bias[512 + c0], bkc1 = bias[512 + c0 + 1];
                const float uc0  = uv[512 + c0],   uc1  = uv[512 + c0 + 1];
                v0 += vv0 * bkc0 + bq0 * uc0;
                v1 += vv0 * bkc1 + bq0 * uc1;
                v2 += vv1 * bkc0 + bq1 * uc0;
                v3 += vv1 * bkc1 + bq1 * uc1;
            }
            v0 *= alpha; v1 *= alpha; v2 *= alpha; v3 *= alpha;
            if (ADD_IDENT) {
                if (r0 == c0)     v0 += 1.f;
                if (r0 == c0 + 1) v1 += 1.f;
                if (r1 == c0)     v2 += 1.f;
                if (r1 == c0 + 1) v3 += 1.f;
            }
            *reinterpret_cast<__half2*>(&D[(size_t)r0 * ldd + c0]) = __floats2half2_rn(v0, v1);
            *reinterpret_cast<__half2*>(&D[(size_t)r1 * ldd + c0]) = __floats2half2_rn(v2, v3);
        }
    }
}

// plain 64x64 GEMM wrapper: grid = BATCH*64 tiles (t = id&63: ix=t&7, iy=t>>3)
template<int BIAS_MODE, bool B_TRANS, bool ADD_IDENT>
__global__ __launch_bounds__(128, 4) void hgemm64_kernel(
    const __half* __restrict__ A, long long sA, int lda,
    const __half* __restrict__ B, long long sB, int ldb,
    __half* __restrict__ D, long long sD, int ldd,
    int K,
    const float* __restrict__ bias, const float* __restrict__ uv,
    float alpha)
{
    extern __shared__ __align__(128) char smem[];
    const int id = blockIdx.x;
    const int b = id >> 6;
    const int t = id & 63;
    gemm64_core<BIAS_MODE, B_TRANS, ADD_IDENT>(
        t & 7, t >> 3, b, smem_u32(smem),
        A, sA, lda, B, sB, ldb, D, sD, ldd, K, bias, uv, alpha);
}

// ---------------- 64x64 symmetric-Gram kernel (NT, K=4096) -------------------
__device__ __forceinline__ void gram64_core(
    int ix, int iy, int bz, uint32_t sbase,
    const __half* __restrict__ X, __half* __restrict__ G)
{
    X += (size_t)bz * C * L;
    G += (size_t)bz * C * C;

    const int bm = iy * 64;
    const int bn = ix * 64;
    const int tid = threadIdx.x;
    const int lane = tid & 31;
    const int wid = tid >> 5;
    const int wm = wid & 1;
    const int wn = wid >> 1;

    const __half* gA = X + (size_t)bm * L;
    const __half* gB = X + (size_t)bn * L;
    const int T = L >> 6;

    const int a_row_lo = lane & 15;
    const int a_sel    = lane >> 4;
    const int b_row_lo = (lane & 7) + ((lane >> 4) << 3);
    const int b_sel    = (lane >> 3) & 1;

    float acc[2][4][4];
    #pragma unroll
    for (int i = 0; i < 2; i++)
        #pragma unroll
        for (int j = 0; j < 4; j++)
            #pragma unroll
            for (int q = 0; q < 4; q++) acc[i][j][q] = 0.f;

    #pragma unroll
    for (int s = 0; s < 2; s++) {
        const uint32_t st = sbase + s * G64_STAGE;
        load_64(gA + s * 64, L, st, tid);
        load_64(gB + s * 64, L, st + 8192, tid);
        CP_COMMIT();
    }

    for (int t = 0; t < T; t++) {
        if (t < T - 1) CP_WAIT1(); else CP_WAIT0();
        __syncthreads();

        if (t + 2 < T) {
            const int s = t + 2;
            const uint32_t st = sbase + (s % 3) * G64_STAGE;
            load_64(gA + s * 64, L, st, tid);
            load_64(gB + s * 64, L, st + 8192, tid);
            CP_COMMIT();
        }

        const uint32_t stA = sbase + (t % 3) * G64_STAGE;
        const uint32_t stB = stA + 8192;

        #pragma unroll
        for (int ks = 0; ks < 4; ks++) {
            uint32_t aF[2][4];
            uint32_t bF[2][4];
            #pragma unroll
            for (int mi = 0; mi < 2; mi++) {
                const int row = wm * 32 + mi * 16 + a_row_lo;
                const int ch  = ks * 2 + a_sel;
                ldsm_x4(aF[mi], stA + (uint32_t)row * 128u + (uint32_t)((ch ^ (row & 7)) << 4));
            }
            #pragma unroll
            for (int nb = 0; nb < 2; nb++) {
                const int row = wn * 32 + nb * 16 + b_row_lo;
                const int ch  = ks * 2 + b_sel;
                ldsm_x4(bF[nb], stB + (uint32_t)row * 128u + (uint32_t)((ch ^ (row & 7)) << 4));
            }
            #pragma unroll
            for (int mi = 0; mi < 2; mi++)
                #pragma unroll
                for (int nj = 0; nj < 4; nj++)
                    mma16816(acc[mi][nj], aF[mi],
                             bF[nj >> 1][(nj & 1) * 2], bF[nj >> 1][(nj & 1) * 2 + 1]);
        }
    }

    const bool mirror = (ix != iy);
    const int m0 = bm + wm * 32;
    const int n0 = bn + wn * 32;
    #pragma unroll
    for (int mi = 0; mi < 2; mi++) {
        const int r0 = m0 + mi * 16 + (lane >> 2);
        const int r1 = r0 + 8;
        #pragma unroll
        for (int nj = 0; nj < 4; nj++) {
            const int c0 = n0 + nj * 8 + (lane & 3) * 2;
            const __half2 h01 = __floats2half2_rn(acc[mi][nj][0], acc[mi][nj][1]);
            const __half2 h23 = __floats2half2_rn(acc[mi][nj][2], acc[mi][nj][3]);
            *reinterpret_cast<__half2*>(&G[(size_t)r0 * C + c0]) = h01;
            *reinterpret_cast<__half2*>(&G[(size_t)r1 * C + c0]) = h23;
            if (mirror) {
                G[(size_t)(c0    ) * C + r0] = __low2half(h01);
                G[(size_t)(c0 + 1) * C + r0] = __high2half(h01);
                G[(size_t)(c0    ) * C + r1] = __low2half(h23);
                G[(size_t)(c0 + 1) * C + r1] = __high2half(h23);
            }
        }
    }
}

__constant__ int G64X[36] = {0,1,2,3,4,5,6,7, 1,2,3,4,5,6,7, 2,3,4,5,6,7,
                             3,4,5,6,7, 4,5,6,7, 5,6,7, 6,7, 7};
__constant__ int G64Y[36] = {0,0,0,0,0,0,0,0, 1,1,1,1,1,1,1, 2,2,2,2,2,2,
                             3,3,3,3,3, 4,4,4,4, 5,5,5, 6,6, 7};

// ids [0,1152): symmetric G tiles. ids [1152,1408): u/v matvec.
__global__ __launch_bounds__(128, 4) void fused_g_uv_kernel(
    const __half* __restrict__ xnh, __half* __restrict__ gram,
    const float* __restrict__ qkvw, const float* __restrict__ qkvb,
    const float* __restrict__ srow, float* __restrict__ uv)
{
    extern __shared__ __align__(128) char smem[];
    const int tid = threadIdx.x;

    int id = blockIdx.x;
    if (id < 1152) {
        const int b = id / 36;
        const int t = id - b * 36;
        gram64_core(G64X[t], G64Y[t], b, smem_u32(smem), xnh, gram);
    } else {
        id -= 1152;
        const int b = id >> 3;
        const int r = (id & 7) * 128 + tid;
        float* ss = (float*)smem;
        for (int i = tid; i < C; i += 128) ss[i] = srow[b * C + i];
        __syncthreads();
        const float4* w4 = (const float4*)(qkvw + (size_t)r * C);
        float d = 0.f;
        #pragma unroll 4
        for (int i = 0; i < C / 4; i++) {
            const float4 wv4 = w4[i];
            d += wv4.x * ss[i*4] + wv4.y * ss[i*4+1]
               + wv4.z * ss[i*4+2] + wv4.w * ss[i*4+3];
        }
        if (r >= 512) d += (float)L * qkvb[r];
        uv[b * 1024 + r] = d;
    }
}

// ---------------- fused MWv 64-tile GEMM (+I) + e matvec ---------------------
// ids [0,2048): MWv tiles. ids [2048,2176): e matvec.
__global__ __launch_bounds__(128, 4) void fused_mwv_kernel(
    const __half* __restrict__ pm, const __half* __restrict__ wv,
    __half* __restrict__ mwv,
    const float* __restrict__ bv, const float* __restrict__ projb,
    float* __restrict__ e)
{
    extern __shared__ __align__(128) char smem[];
    const long long sATT = (long long)C * C;
    const int tid = threadIdx.x;

    int id = blockIdx.x;
    if (id < 2048) {
        const int b = id >> 6;
        const int t = id & 63;
        gemm64_core<0, true, true>(
            t & 7, t >> 3, b, smem_u32(smem),
            pm, sATT, C, wv, 0LL, C,
            mwv, sATT, C, C, nullptr, nullptr, 1.0f);
    } else {
        id -= 2048;
        const int b = id >> 2;
        const int o = (id & 3) * 128 + tid;
        float* sbv = (float*)smem;
        for (int i = tid; i < C; i += 128) sbv[i] = bv[i];
        __syncthreads();
        const __half2* m2 = (const __half2*)(pm + (size_t)b * C * C + (size_t)o * C);
        float d = 0.f;
        #pragma unroll 4
        for (int i = 0; i < C / 2; i++) {
            const float2 mv = __half22float2(m2[i]);
            d += mv.x * sbv[i*2] + mv.y * sbv[i*2+1];
        }
        e[b * C + o] = d + projb[o];
    }
}

// ---------------------------------------------------------------------------
extern "C" void kernel_launch(void* const* d_in, const int* in_sizes, int n_in,
                              void* d_out, int out_size)
{
    const float* x      = (const float*)d_in[0];
    const float* gn_w   = (const float*)d_in[1];
    const float* gn_b   = (const float*)d_in[2];
    const float* qkv_w  = (const float*)d_in[3];
    const float* qkv_b  = (const float*)d_in[4];
    const float* proj_w = (const float*)d_in[5];
    const float* proj_b = (const float*)d_in[6];
    float* out = (float*)d_out;

    __half *xnh, *gram, *t1, *logits, *attn, *pm, *mwv, *wh;
    float *srow, *uv, *e;
    cudaGetSymbolAddress((void**)&xnh,    g_xnh);
    cudaGetSymbolAddress((void**)&gram,   g_gram);
    cudaGetSymbolAddress((void**)&t1,     g_t1);
    cudaGetSymbolAddress((void**)&logits, g_logits);
    cudaGetSymbolAddress((void**)&attn,   g_attn);
    cudaGetSymbolAddress((void**)&pm,     g_pm);
    cudaGetSymbolAddress((void**)&mwv,    g_mwv);
    cudaGetSymbolAddress((void**)&wh,     g_wh);
    cudaGetSymbolAddress((void**)&srow,   g_s);
    cudaGetSymbolAddress((void**)&uv,     g_uv);
    cudaGetSymbolAddress((void**)&e,      g_e);

    cudaFuncSetAttribute(hgemm64_kernel<0, false, false>, cudaFuncAttributeMaxDynamicSharedMemorySize, G64_SMEM);
    cudaFuncSetAttribute(hgemm64_kernel<3, false, false>, cudaFuncAttributeMaxDynamicSharedMemorySize, G64_SMEM);
    cudaFuncSetAttribute(hgemm64_kernel<0, true,  false>, cudaFuncAttributeMaxDynamicSharedMemorySize, G64_SMEM);
    cudaFuncSetAttribute(hgemm_out_kernel<float>, cudaFuncAttributeMaxDynamicSharedMemorySize, GEMM_SMEM);
    cudaFuncSetAttribute(fused_g_uv_kernel, cudaFuncAttributeMaxDynamicSharedMemorySize, G64_SMEM);
    cudaFuncSetAttribute(fused_mwv_kernel,  cudaFuncAttributeMaxDynamicSharedMemorySize, G64_SMEM);

    const long long sXN  = (long long)C * L;
    const long long sATT = (long long)C * C;

    // 1) GroupNorm -> xnh fp16 (+ row sums s, + weight convert)
    gn_cvt_kernel<<<BATCH * GROUPS + 1024, 256>>>(
        x, gn_w, gn_b, xnh, qkv_w, proj_w, wh, srow);

    // 2) fused: G = xn·xn^T (symmetric 64x64 tiles + mirror) + u/v matvecs
    fused_g_uv_kernel<<<1152 + 256, 128, G64_SMEM>>>(
        xnh, gram, qkv_w, qkv_b, srow, uv);

    // 3) T1 = Wq·G  (NT 64-tiles, M=N=K=512)
    hgemm64_kernel<0, false, false><<<BATCH * 64, 128, G64_SMEM>>>(
        wh, 0LL, C, gram, sATT, C, t1, sATT, C, C,
        nullptr, nullptr, 1.0f);

    // 4) logits = (T1·Wk^T + v⊗bk + bq⊗u) / 64  (NT 64-tiles, rank-1 epilogue)
    hgemm64_kernel<3, false, false><<<BATCH * 64, 128, G64_SMEM>>>(
        t1, sATT, C, wh + (size_t)512 * C, 0LL, C, logits, sATT, C, C,
        qkv_b, uv, 0.015625f);

    // 5) softmax -> attn fp16
    softmax512_kernel<<<BATCH * C, 128>>>(logits, attn);

    // 6) M[o,k] = Σ_q P[o,q]·attn[q,k]  (trans-B 64-tiles)
    hgemm64_kernel<0, true, false><<<BATCH * 64, 128, G64_SMEM>>>(
        wh + (size_t)3 * C * C, 0LL, C, attn, sATT, C, pm, sATT, C, C,
        nullptr, nullptr, 1.0f);

    // 7) fused: MWv = M·Wv + I (trans-B 64-tiles) + e = M·bv + proj_b
    fused_mwv_kernel<<<2048 + 128, 128, G64_SMEM>>>(
        pm, wh + (size_t)1024 * C, mwv,
        qkv_b + 1024, proj_b, e);

    // 8) out[o,l] = (MWv+I)[o,:]·xn[:,l] + e[b][o]  (trans-B 128-tiles)
    {
        dim3 grid(L / 128, C / 128, BATCH);
        hgemm_out_kernel<float><<<grid, 128, GEMM_SMEM>>>(
            mwv, sATT, C, xnh, sXN, L, out, sXN, L, C,
            e, (long long)C);
    }
}